// round 4
// baseline (speedup 1.0000x reference)
#include <cuda_runtime.h>
#include <cstdint>

// Problem constants (fixed by setup_inputs)
#define BS 8
#define M  4096
#define T  32
#define E  65536
#define NROWS (BS * M)          // 32768
#define DEG_CAP 64              // Poisson(16) total degree; P(>64) ~ 1e-20

// Scratch: per-row edge count + packed u16 target lists (32768 x 64 = 4 MB).
// Device globals are zero-initialized at module load; the agg kernel resets
// counts to zero after use, so every launch starts from a clean state with
// no explicit zeroing pass.
__device__ unsigned g_count[NROWS];
__device__ ushort4  g_list4[NROWS * (DEG_CAP / 4)];

// ---------------------------------------------------------------------------
// Kernel 1: append every edge (duplicates included) to its source row's list.
// One atomicAdd per edge. Dedup is deferred to the agg kernel (dups are
// ~0.02% of edges). A_coo is int32, layout (bs, 2, E) row-major.
// ---------------------------------------------------------------------------
__global__ void nil_build_kernel(const int* __restrict__ coo,
                                 float* __restrict__ out) {
    unsigned tid = blockIdx.x * blockDim.x + threadIdx.x;  // < BS*E
    if (tid == 0) *out = 0.0f;
    unsigned b = tid >> 16;        // / E
    unsigned e = tid & (E - 1);
    int s = coo[(size_t)b * 2 * E + e];
    int t = coo[(size_t)b * 2 * E + E + e];
    unsigned src = (unsigned)s & (M - 1);   // % M (power of two)
    unsigned tgt = (unsigned)t & (M - 1);
    unsigned row = b * M + src;

    unsigned pos = atomicAdd(&g_count[row], 1u);
    if (pos < DEG_CAP)
        reinterpret_cast<unsigned short*>(g_list4)[row * DEG_CAP + pos] =
            (unsigned short)tgt;
}

// ---------------------------------------------------------------------------
// Kernel 2: one warp per (b,i) row, lane == t.
//   1) register-dedup the row's edge list (match_any -> 64-bit keep mask,
//      warp-uniform, exactly reproducing jnp set(1.0) semantics)
//   2) acc[t] = yb[b,i,t] (identity) + sum over kept entries j of yb[b,j,t]
//   3) reg += relu(yb[b,i,t+1] - acc[t])
//   4) reset g_count[row] = 0 for the next launch/replay
// Gathers run 4-wide (MLP=4) from one uniform 8B list load per iteration.
// ---------------------------------------------------------------------------
__global__ void nil_agg_kernel(const float* __restrict__ y,
                               float* __restrict__ out) {
    const unsigned FULL = 0xffffffffu;
    unsigned gwarp = (blockIdx.x * blockDim.x + threadIdx.x) >> 5;  // row id
    unsigned lane  = threadIdx.x & 31;

    unsigned b = gwarp >> 12;        // / M
    unsigned i = gwarp & (M - 1);

    const float* yb = y + (size_t)b * (M * T);
    float self = yb[(size_t)i * T + lane];
    float acc  = self;                          // identity term

    int deg = (int)g_count[gwarp];
    if (deg > DEG_CAP) deg = DEG_CAP;
    if (lane == 0) g_count[gwarp] = 0;          // self-clean for next launch

    const unsigned short* lst =
        reinterpret_cast<const unsigned short*>(g_list4) +
        (size_t)gwarp * DEG_CAP;
    const ushort4* lst4 = g_list4 + (size_t)gwarp * (DEG_CAP / 4);

    // ---- dedup: build 64-bit keep mask (first occurrence wins) ----
    // Lane k owns entries k and k+32. Sentinels are unique per lane and
    // disjoint from real values (<4096) and from each other.
    unsigned e0 = (lane < (unsigned)deg) ? (unsigned)lst[lane] : (0x10000u | lane);
    unsigned m0 = __match_any_sync(FULL, e0);
    bool k0 = (lane < (unsigned)deg) && ((m0 & ((1u << lane) - 1u)) == 0u);
    unsigned long long keep = (unsigned long long)__ballot_sync(FULL, k0);

    if (deg > 32) {                              // warp-uniform branch (rare)
        unsigned e1 = (lane + 32 < (unsigned)deg) ? (unsigned)lst[lane + 32]
                                                  : (0x20000u | lane);
        unsigned m1 = __match_any_sync(FULL, e1);
        bool k1 = (lane + 32 < (unsigned)deg) &&
                  ((m1 & ((1u << lane) - 1u)) == 0u);
        // cross-half check: entry lane+32 duplicates something in [0,32)
        bool dup = false;
        #pragma unroll
        for (int l = 0; l < 32; ++l) {
            unsigned v = __shfl_sync(FULL, e0, l);
            dup = dup || (v == e1);
        }
        k1 = k1 && !dup;
        keep |= ((unsigned long long)__ballot_sync(FULL, k1)) << 32;
    }

    // ---- gather & accumulate (always gather, keep-bit is warp-uniform) ----
    for (int k = 0; k < deg; k += 4) {
        ushort4 q = lst4[k >> 2];                // uniform 8B load
        float v0 = yb[(size_t)q.x * T + lane];
        float v1 = yb[(size_t)q.y * T + lane];
        float v2 = yb[(size_t)q.z * T + lane];
        float v3 = yb[(size_t)q.w * T + lane];
        if ((keep >> (k + 0)) & 1ull) acc += v0;
        if ((keep >> (k + 1)) & 1ull) acc += v1;
        if ((keep >> (k + 2)) & 1ull) acc += v2;
        if ((keep >> (k + 3)) & 1ull) acc += v3;
    }

    // diff[t] = yb[b,i,t+1] - acc[t], t = lane in [0,31)
    float ynext = __shfl_down_sync(FULL, self, 1);
    float r = (lane < 31) ? fmaxf(ynext - acc, 0.0f) : 0.0f;

    // warp reduce
    #pragma unroll
    for (int o = 16; o > 0; o >>= 1)
        r += __shfl_down_sync(FULL, r, o);

    // block reduce (8 warps/block) -> one atomic per block
    __shared__ float sred[8];
    unsigned wib = threadIdx.x >> 5;
    if (lane == 0) sred[wib] = r;
    __syncthreads();
    if (threadIdx.x < 8) {
        float v = sred[threadIdx.x];
        #pragma unroll
        for (int o = 4; o > 0; o >>= 1)
            v += __shfl_down_sync(0x000000ffu, v, o);
        if (threadIdx.x == 0) atomicAdd(out, v);
    }
}

// ---------------------------------------------------------------------------
// kernel_launch: build -> aggregate. Plain launches, no allocs/syncs.
// ---------------------------------------------------------------------------
extern "C" void kernel_launch(void* const* d_in, const int* in_sizes, int n_in,
                              void* d_out, int out_size) {
    (void)in_sizes; (void)n_in; (void)out_size;
    const float* y   = (const float*)d_in[0];
    const int*   coo = (const int*)d_in[1];
    float*       out = (float*)d_out;

    nil_build_kernel<<<(BS * E) / 256, 256>>>(coo, out);
    nil_agg_kernel<<<NROWS / 8, 256>>>(y, out);
}

// round 5
// speedup vs baseline: 1.6574x; 1.6574x over previous
#include <cuda_runtime.h>
#include <cstdint>

// Problem constants (fixed by setup_inputs)
#define BS 8
#define M  4096
#define T  32
#define E  65536
#define WORDS_PER_ROW (M / 32)             // 128
#define NROWS (BS * M)                     // 32768
#define MASK_WORDS (NROWS * WORDS_PER_ROW) // 4,194,304 u32 = 16 MB
#define DEG_CAP 64                         // Poisson(16) distinct deg; P(>64) ~ 1e-20

// Scratch. Device globals start zeroed at module load; the agg kernel restores
// the zero state (clears the exact mask words that were set + the counts), so
// no explicit zeroing pass is ever needed.
__device__ uint4    g_mask4[MASK_WORDS / 4];   // dedup bitmask, row-major 128w/row
__device__ unsigned g_count[NROWS];            // distinct-neighbor counts
__device__ ushort4  g_list4[NROWS * (DEG_CAP / 4)];  // packed u16 neighbor lists

// ---------------------------------------------------------------------------
// Kernel 1: dedup + append. atomicOr's old value identifies the first setter
// of each (row,tgt) bit -> exact jnp .at[].set(1.0) set semantics; only the
// first setter appends to the row list. A_coo is int32, layout (bs,2,E).
// ---------------------------------------------------------------------------
__global__ void nil_build_kernel(const int* __restrict__ coo,
                                 float* __restrict__ out) {
    unsigned tid = blockIdx.x * blockDim.x + threadIdx.x;  // < BS*E
    if (tid == 0) *out = 0.0f;
    unsigned b = tid >> 16;        // / E
    unsigned e = tid & (E - 1);
    int s = coo[(size_t)b * 2 * E + e];
    int t = coo[(size_t)b * 2 * E + E + e];
    unsigned src = (unsigned)s & (M - 1);   // % M (power of two)
    unsigned tgt = (unsigned)t & (M - 1);
    unsigned row = b * M + src;

    unsigned* mask = reinterpret_cast<unsigned*>(g_mask4);
    unsigned bit = 1u << (tgt & 31);
    unsigned old = atomicOr(&mask[((size_t)row << 7) + (tgt >> 5)], bit);
    if (!(old & bit)) {
        unsigned pos = atomicAdd(&g_count[row], 1u);
        if (pos < DEG_CAP)
            reinterpret_cast<unsigned short*>(g_list4)[row * DEG_CAP + pos] =
                (unsigned short)tgt;
    }
}

// ---------------------------------------------------------------------------
// Kernel 2: one warp per (b,i) row, lane == t.
//   acc[t] = yb[b,i,t] (identity) + sum over distinct neighbors j of yb[b,j,t]
//   reg   += relu(yb[b,i,t+1] - acc[t]), t in [0,31)
// All 8 list quads are loaded up front (stale entries are <4096 -> in-bounds,
// and never accumulated), so the 32 gathers front-batch with high MLP. deg>32
// is a warp-uniform rare tail. The kernel also self-cleans the scratch:
// clears the mask words named by its list and zeroes its count.
// ---------------------------------------------------------------------------
__global__ void nil_agg_kernel(const float* __restrict__ y,
                               float* __restrict__ out) {
    const unsigned FULL = 0xffffffffu;
    unsigned gwarp = (blockIdx.x * blockDim.x + threadIdx.x) >> 5;  // row id
    unsigned lane  = threadIdx.x & 31;

    unsigned b = gwarp >> 12;        // / M
    unsigned i = gwarp & (M - 1);

    const float* yb = y + (size_t)b * (M * T);
    float self = yb[(size_t)i * T + lane];
    float acc  = self;                          // identity term

    int deg = (int)g_count[gwarp];
    if (deg > DEG_CAP) deg = DEG_CAP;

    const unsigned short* lst =
        reinterpret_cast<const unsigned short*>(g_list4) +
        (size_t)gwarp * DEG_CAP;
    const ushort4* lst4 = g_list4 + (size_t)gwarp * (DEG_CAP / 4);

    // ---- self-clean scratch (independent of gathers; overlaps with them) ----
    {
        unsigned* mask = reinterpret_cast<unsigned*>(g_mask4) +
                         ((size_t)gwarp << 7);
        if ((int)lane < deg)      mask[lst[lane] >> 5] = 0u;
        if ((int)lane + 32 < deg) mask[lst[lane + 32] >> 5] = 0u;
        if (lane == 0)            g_count[gwarp] = 0u;
    }

    // ---- front-batched list loads (uniform 8B each, unconditional) ----
    ushort4 q[8];
    #pragma unroll
    for (int p = 0; p < 8; ++p) q[p] = lst4[p];

    // ---- gathers: quad-predicated loads, element-predicated adds ----
    #pragma unroll
    for (int p = 0; p < 8; ++p) {
        int k = p * 4;
        if (k < deg) {                           // warp-uniform predicate
            float v0 = yb[(size_t)q[p].x * T + lane];
            float v1 = yb[(size_t)q[p].y * T + lane];
            float v2 = yb[(size_t)q[p].z * T + lane];
            float v3 = yb[(size_t)q[p].w * T + lane];
            acc += v0;
            if (k + 1 < deg) acc += v1;
            if (k + 2 < deg) acc += v2;
            if (k + 3 < deg) acc += v3;
        }
    }

    if (deg > 32) {                              // warp-uniform, ~0.01% of rows
        for (int k = 32; k < deg; k += 4) {
            ushort4 e = lst4[k >> 2];
            float v0 = yb[(size_t)e.x * T + lane];
            float v1 = yb[(size_t)e.y * T + lane];
            float v2 = yb[(size_t)e.z * T + lane];
            float v3 = yb[(size_t)e.w * T + lane];
            acc += v0;
            if (k + 1 < deg) acc += v1;
            if (k + 2 < deg) acc += v2;
            if (k + 3 < deg) acc += v3;
        }
    }

    // diff[t] = yb[b,i,t+1] - acc[t], t = lane in [0,31)
    float ynext = __shfl_down_sync(FULL, self, 1);
    float r = (lane < 31) ? fmaxf(ynext - acc, 0.0f) : 0.0f;

    // warp reduce
    #pragma unroll
    for (int o = 16; o > 0; o >>= 1)
        r += __shfl_down_sync(FULL, r, o);

    // block reduce (8 warps/block) -> one atomic per block
    __shared__ float sred[8];
    unsigned wib = threadIdx.x >> 5;
    if (lane == 0) sred[wib] = r;
    __syncthreads();
    if (threadIdx.x < 8) {
        float v = sred[threadIdx.x];
        #pragma unroll
        for (int o = 4; o > 0; o >>= 1)
            v += __shfl_down_sync(0x000000ffu, v, o);
        if (threadIdx.x == 0) atomicAdd(out, v);
    }
}

// ---------------------------------------------------------------------------
// kernel_launch: build -> aggregate. Plain launches, no allocs/syncs.
// ---------------------------------------------------------------------------
extern "C" void kernel_launch(void* const* d_in, const int* in_sizes, int n_in,
                              void* d_out, int out_size) {
    (void)in_sizes; (void)n_in; (void)out_size;
    const float* y   = (const float*)d_in[0];
    const int*   coo = (const int*)d_in[1];
    float*       out = (float*)d_out;

    nil_build_kernel<<<(BS * E) / 256, 256>>>(coo, out);
    nil_agg_kernel<<<NROWS / 8, 256>>>(y, out);
}

// round 6
// speedup vs baseline: 1.9102x; 1.1525x over previous
#include <cuda_runtime.h>
#include <cstdint>

// Problem constants (fixed by setup_inputs)
#define BS 8
#define M  4096
#define T  32
#define E  65536
#define WORDS_PER_ROW (M / 32)             // 128
#define NROWS (BS * M)                     // 32768
#define MASK_WORDS (NROWS * WORDS_PER_ROW) // 4,194,304 u32 = 16 MB
#define DEG_CAP 64                         // Poisson(16) distinct deg; P(>64) ~ 1e-20

// Scratch. Device globals start zeroed at module load; the agg kernel restores
// the zero state (clears exactly the mask words its list names + the counts),
// so no explicit zeroing pass is ever needed.
__device__ uint4    g_mask4[MASK_WORDS / 4];        // dedup bitmask, 128 w/row
__device__ unsigned g_count[NROWS];                 // distinct-neighbor counts
__device__ ushort4  g_list4[NROWS * (DEG_CAP / 4)]; // packed u16 neighbor lists

// ---------------------------------------------------------------------------
// Kernel 1: dedup + append, 2 edges per thread (independent atomic chains ->
// atomic MLP=2). atomicOr's old value identifies the first setter of each
// (row,tgt) bit -> exact jnp .at[].set(1.0) set semantics; only the first
// setter appends. A_coo is int32, layout (bs, 2, E) row-major; consecutive
// edge pairs give aligned int2 loads from both the src and tgt streams.
// ---------------------------------------------------------------------------
__global__ void nil_build_kernel(const int* __restrict__ coo,
                                 float* __restrict__ out) {
    unsigned tid = blockIdx.x * blockDim.x + threadIdx.x;  // < BS*E/2
    if (tid == 0) *out = 0.0f;
    unsigned b  = tid >> 15;               // / (E/2)
    unsigned e2 = (tid & (E / 2 - 1)) * 2; // even edge index within batch

    const int2* srcs = reinterpret_cast<const int2*>(coo + (size_t)b * 2 * E);
    const int2* tgts = reinterpret_cast<const int2*>(coo + (size_t)b * 2 * E + E);
    int2 sp = srcs[e2 >> 1];
    int2 tp = tgts[e2 >> 1];

    unsigned* mask = reinterpret_cast<unsigned*>(g_mask4);

    unsigned src0 = (unsigned)sp.x & (M - 1), tgt0 = (unsigned)tp.x & (M - 1);
    unsigned src1 = (unsigned)sp.y & (M - 1), tgt1 = (unsigned)tp.y & (M - 1);
    unsigned row0 = b * M + src0,             row1 = b * M + src1;
    unsigned bit0 = 1u << (tgt0 & 31),        bit1 = 1u << (tgt1 & 31);

    // Two independent Or chains issue back-to-back (latency overlap).
    unsigned old0 = atomicOr(&mask[((size_t)row0 << 7) + (tgt0 >> 5)], bit0);
    unsigned old1 = atomicOr(&mask[((size_t)row1 << 7) + (tgt1 >> 5)], bit1);

    unsigned short* lst = reinterpret_cast<unsigned short*>(g_list4);
    if (!(old0 & bit0)) {
        unsigned pos = atomicAdd(&g_count[row0], 1u);
        if (pos < DEG_CAP) lst[row0 * DEG_CAP + pos] = (unsigned short)tgt0;
    }
    if (!(old1 & bit1)) {
        unsigned pos = atomicAdd(&g_count[row1], 1u);
        if (pos < DEG_CAP) lst[row1 * DEG_CAP + pos] = (unsigned short)tgt1;
    }
}

// ---------------------------------------------------------------------------
// Kernel 2: one warp per (b,i) row, lane == t.
//   acc[t] = yb[b,i,t] (identity) + sum over distinct neighbors j of yb[b,j,t]
//   reg   += relu(yb[b,i,t+1] - acc[t]), t in [0,31)
// EARLY EXIT: y >= 0, so acc is monotone nondecreasing; once every lane has
// acc >= ynext, all remaining relu terms are exactly 0 -> stop gathering.
// (~95% of warps stop after the first quad of neighbors.)
// The kernel also self-cleans the scratch up front: clears the mask words
// named by its list and zeroes its count.
// ---------------------------------------------------------------------------
__global__ void nil_agg_kernel(const float* __restrict__ y,
                               float* __restrict__ out) {
    const unsigned FULL = 0xffffffffu;
    unsigned gwarp = (blockIdx.x * blockDim.x + threadIdx.x) >> 5;  // row id
    unsigned lane  = threadIdx.x & 31;

    unsigned b = gwarp >> 12;        // / M
    unsigned i = gwarp & (M - 1);

    const float* yb = y + (size_t)b * (M * T);
    float self = yb[(size_t)i * T + lane];
    float acc  = self;                          // identity term

    int deg = (int)g_count[gwarp];
    if (deg > DEG_CAP) deg = DEG_CAP;

    const unsigned short* lst =
        reinterpret_cast<const unsigned short*>(g_list4) +
        (size_t)gwarp * DEG_CAP;
    const ushort4* lst4 = g_list4 + (size_t)gwarp * (DEG_CAP / 4);

    // ---- self-clean scratch (must complete regardless of early exit) ----
    {
        unsigned* mask = reinterpret_cast<unsigned*>(g_mask4) +
                         ((size_t)gwarp << 7);
        if ((int)lane < deg)      mask[lst[lane] >> 5] = 0u;
        if ((int)lane + 32 < deg) mask[lst[lane + 32] >> 5] = 0u;
        if (lane == 0)            g_count[gwarp] = 0u;
    }

    // ynext[t] = yb[b,i,t+1]; lane 31 is a dead lane (unused term)
    float ynext = __shfl_down_sync(FULL, self, 1);
    bool tvalid = (lane < 31);

    // ---- gather loop with monotone early exit ----
    for (int k = 0; k < deg; k += 4) {
        // stop as soon as no lane can still produce a nonzero relu term
        if (__ballot_sync(FULL, tvalid && acc < ynext) == 0u) break;
        ushort4 q = lst4[k >> 2];                // uniform 8B list load
        float v0 = yb[(size_t)q.x * T + lane];
        float v1 = yb[(size_t)q.y * T + lane];
        float v2 = yb[(size_t)q.z * T + lane];
        float v3 = yb[(size_t)q.w * T + lane];
        acc += v0;
        if (k + 1 < deg) acc += v1;
        if (k + 2 < deg) acc += v2;
        if (k + 3 < deg) acc += v3;
    }

    // exact: early-exited lanes have acc >= ynext -> relu term is 0
    float r = tvalid ? fmaxf(ynext - acc, 0.0f) : 0.0f;

    // warp reduce
    #pragma unroll
    for (int o = 16; o > 0; o >>= 1)
        r += __shfl_down_sync(FULL, r, o);

    // block reduce (8 warps/block) -> one atomic per block
    __shared__ float sred[8];
    unsigned wib = threadIdx.x >> 5;
    if (lane == 0) sred[wib] = r;
    __syncthreads();
    if (threadIdx.x < 8) {
        float v = sred[threadIdx.x];
        #pragma unroll
        for (int o = 4; o > 0; o >>= 1)
            v += __shfl_down_sync(0x000000ffu, v, o);
        if (threadIdx.x == 0) atomicAdd(out, v);
    }
}

// ---------------------------------------------------------------------------
// kernel_launch: build -> aggregate. Plain launches, no allocs/syncs.
// ---------------------------------------------------------------------------
extern "C" void kernel_launch(void* const* d_in, const int* in_sizes, int n_in,
                              void* d_out, int out_size) {
    (void)in_sizes; (void)n_in; (void)out_size;
    const float* y   = (const float*)d_in[0];
    const int*   coo = (const int*)d_in[1];
    float*       out = (float*)d_out;

    nil_build_kernel<<<(BS * E / 2) / 256, 256>>>(coo, out);
    nil_agg_kernel<<<NROWS / 8, 256>>>(y, out);
}

// round 7
// speedup vs baseline: 1.9588x; 1.0255x over previous
#include <cuda_runtime.h>
#include <cstdint>

// Problem constants (fixed by setup_inputs)
#define BS 8
#define M  4096
#define T  32
#define E  65536
#define WORDS_PER_ROW (M / 32)             // 128
#define NROWS (BS * M)                     // 32768
#define MASK_WORDS (NROWS * WORDS_PER_ROW) // 4,194,304 u32 = 16 MB
#define DEG_CAP 64                         // Poisson(16) distinct deg; P(>64) ~ 1e-20

// Scratch. Device globals start zeroed at module load; the agg kernel restores
// the zero state (clears exactly the mask words its list names + the counts),
// so no explicit zeroing pass is ever needed.
__device__ uint4    g_mask4[MASK_WORDS / 4];        // dedup bitmask, 128 w/row
__device__ unsigned g_count[NROWS];                 // distinct-neighbor counts
__device__ ushort4  g_list4[NROWS * (DEG_CAP / 4)]; // packed u16 neighbor lists

// ---------------------------------------------------------------------------
// Kernel 1: dedup + append, 4 edges per thread (4 independent atomicOr chains
// in flight). atomicOr's old value identifies the first setter of each
// (row,tgt) bit -> exact jnp .at[].set(1.0) set semantics; only the first
// setter appends. A_coo is int32, layout (bs, 2, E) row-major; 4 consecutive
// edges give aligned int4 loads from both the src and tgt streams.
// ---------------------------------------------------------------------------
__global__ void nil_build_kernel(const int* __restrict__ coo,
                                 float* __restrict__ out) {
    unsigned tid = blockIdx.x * blockDim.x + threadIdx.x;  // < BS*E/4
    if (tid == 0) *out = 0.0f;
    unsigned b  = tid >> 14;               // / (E/4)
    unsigned e4 = tid & (E / 4 - 1);       // quad index within batch

    const int4* srcs = reinterpret_cast<const int4*>(coo + (size_t)b * 2 * E);
    const int4* tgts = reinterpret_cast<const int4*>(coo + (size_t)b * 2 * E + E);
    int4 sp = srcs[e4];
    int4 tp = tgts[e4];

    unsigned* mask = reinterpret_cast<unsigned*>(g_mask4);
    unsigned short* lst = reinterpret_cast<unsigned short*>(g_list4);

    unsigned src[4] = {(unsigned)sp.x & (M-1), (unsigned)sp.y & (M-1),
                       (unsigned)sp.z & (M-1), (unsigned)sp.w & (M-1)};
    unsigned tgt[4] = {(unsigned)tp.x & (M-1), (unsigned)tp.y & (M-1),
                       (unsigned)tp.z & (M-1), (unsigned)tp.w & (M-1)};
    unsigned row[4], bit[4], old[4];
    #pragma unroll
    for (int p = 0; p < 4; ++p) {
        row[p] = b * M + src[p];
        bit[p] = 1u << (tgt[p] & 31);
    }
    // 4 independent Or chains issue back-to-back (latency overlap, MLP=4)
    #pragma unroll
    for (int p = 0; p < 4; ++p)
        old[p] = atomicOr(&mask[((size_t)row[p] << 7) + (tgt[p] >> 5)], bit[p]);
    #pragma unroll
    for (int p = 0; p < 4; ++p) {
        if (!(old[p] & bit[p])) {
            unsigned pos = atomicAdd(&g_count[row[p]], 1u);
            if (pos < DEG_CAP)
                lst[row[p] * DEG_CAP + pos] = (unsigned short)tgt[p];
        }
    }
}

// ---------------------------------------------------------------------------
// Kernel 2: one warp per (b,i) row, lane == t.
//   acc[t] = yb[b,i,t] (identity) + sum over distinct neighbors j of yb[b,j,t]
//   reg   += relu(yb[b,i,t+1] - acc[t]), t in [0,31)
// EARLY EXIT: y >= 0 so acc is monotone; once every lane has acc >= ynext the
// remaining relu terms are exactly 0. Quad 0 is gathered unconditionally
// (pre-add exit is probabilistically impossible), the exit ballot runs only
// between subsequent quads, and dead warps skip the whole reduce chain.
// The kernel self-cleans the scratch (mask words named by its list + count).
// ---------------------------------------------------------------------------
__global__ void nil_agg_kernel(const float* __restrict__ y,
                               float* __restrict__ out) {
    const unsigned FULL = 0xffffffffu;
    unsigned gwarp = (blockIdx.x * blockDim.x + threadIdx.x) >> 5;  // row id
    unsigned lane  = threadIdx.x & 31;

    unsigned b = gwarp >> 12;        // / M
    unsigned i = gwarp & (M - 1);

    const ushort4* lst4 = g_list4 + (size_t)gwarp * (DEG_CAP / 4);
    const unsigned short* lst =
        reinterpret_cast<const unsigned short*>(g_list4) + (size_t)gwarp * DEG_CAP;
    const float* yb = y + (size_t)b * (M * T);

    // ---- front-issue all independent loads (count / first quad / self) ----
    int deg = (int)g_count[gwarp];           // warp-uniform 4B load
    ushort4 q0 = lst4[0];                    // warp-uniform 8B load
    float self = yb[(size_t)i * T + lane];   // coalesced 128B load

    if (deg > DEG_CAP) deg = DEG_CAP;

    // ---- self-clean scratch (independent of the gather chain) ----
    {
        unsigned* mask = reinterpret_cast<unsigned*>(g_mask4) +
                         ((size_t)gwarp << 7);
        if ((int)lane < deg)      mask[lst[lane] >> 5] = 0u;
        if ((int)lane + 32 < deg) mask[lst[lane + 32] >> 5] = 0u;
        if (lane == 0)            g_count[gwarp] = 0u;
    }

    float acc = self;                        // identity term
    float ynext = __shfl_down_sync(FULL, self, 1);
    bool tvalid = (lane < 31);

    // ---- quad 0: unconditional gather (stale entries in-bounds, adds
    //      predicated), no pre-ballot ----
    {
        float v0 = yb[(size_t)q0.x * T + lane];
        float v1 = yb[(size_t)q0.y * T + lane];
        float v2 = yb[(size_t)q0.z * T + lane];
        float v3 = yb[(size_t)q0.w * T + lane];
        if (deg > 0) acc += v0;
        if (deg > 1) acc += v1;
        if (deg > 2) acc += v2;
        if (deg > 3) acc += v3;
    }

    // ---- remaining quads with monotone early exit ----
    unsigned pend = __ballot_sync(FULL, tvalid && acc < ynext);
    for (int k = 4; k < deg && pend; k += 4) {
        ushort4 q = lst4[k >> 2];
        float v0 = yb[(size_t)q.x * T + lane];
        float v1 = yb[(size_t)q.y * T + lane];
        float v2 = yb[(size_t)q.z * T + lane];
        float v3 = yb[(size_t)q.w * T + lane];
        acc += v0;
        if (k + 1 < deg) acc += v1;
        if (k + 2 < deg) acc += v2;
        if (k + 3 < deg) acc += v3;
        pend = __ballot_sync(FULL, tvalid && acc < ynext);
    }

    // ---- reduce only if some lane can contribute (pend warp-uniform) ----
    float wsum = 0.0f;
    if (pend) {
        float r = tvalid ? fmaxf(ynext - acc, 0.0f) : 0.0f;
        #pragma unroll
        for (int o = 16; o > 0; o >>= 1)
            r += __shfl_down_sync(FULL, r, o);
        wsum = r;
    }

    // block reduce (8 warps/block) -> at most one atomic per block
    __shared__ float sred[8];
    unsigned wib = threadIdx.x >> 5;
    if (lane == 0) sred[wib] = wsum;
    __syncthreads();
    if (threadIdx.x < 8) {
        float v = sred[threadIdx.x];
        #pragma unroll
        for (int o = 4; o > 0; o >>= 1)
            v += __shfl_down_sync(0x000000ffu, v, o);
        if (threadIdx.x == 0 && v != 0.0f) atomicAdd(out, v);
    }
}

// ---------------------------------------------------------------------------
// kernel_launch: build -> aggregate. Plain launches, no allocs/syncs.
// ---------------------------------------------------------------------------
extern "C" void kernel_launch(void* const* d_in, const int* in_sizes, int n_in,
                              void* d_out, int out_size) {
    (void)in_sizes; (void)n_in; (void)out_size;
    const float* y   = (const float*)d_in[0];
    const int*   coo = (const int*)d_in[1];
    float*       out = (float*)d_out;

    nil_build_kernel<<<(BS * E / 4) / 256, 256>>>(coo, out);
    nil_agg_kernel<<<NROWS / 8, 256>>>(y, out);
}

// round 8
// speedup vs baseline: 2.0639x; 1.0536x over previous
#include <cuda_runtime.h>
#include <cstdint>

// Problem constants (fixed by setup_inputs)
#define BS 8
#define M  4096
#define T  32
#define E  65536
#define NROWS (BS * M)          // 32768
#define DEG_CAP 64              // Poisson(16) row degree; P(>64) ~ 1e-20

// Scratch. Device globals start zeroed at module load; agg resets counts after
// consuming them, so every replay starts clean. List entries are overwritten
// each run; stale tails are never read (bounded by deg) and are always < M.
__device__ unsigned g_count[NROWS];                 // per-row edge counts
__device__ ushort4  g_list4[NROWS * (DEG_CAP / 4)]; // packed u16 target lists

// ---------------------------------------------------------------------------
// Kernel 1: append every edge (dups included -> dedup in agg). ONE atomic per
// edge — build is atomic-throughput bound, so this is the minimal form.
// A_coo is int32, layout (bs, 2, E) row-major.
// ---------------------------------------------------------------------------
__global__ void nil_build_kernel(const int* __restrict__ coo,
                                 float* __restrict__ out) {
    unsigned tid = blockIdx.x * blockDim.x + threadIdx.x;  // < BS*E
    if (tid == 0) *out = 0.0f;
    unsigned b = tid >> 16;        // / E
    unsigned e = tid & (E - 1);
    int s = coo[(size_t)b * 2 * E + e];
    int t = coo[(size_t)b * 2 * E + E + e];
    unsigned src = (unsigned)s & (M - 1);   // % M (power of two)
    unsigned tgt = (unsigned)t & (M - 1);
    unsigned row = b * M + src;

    unsigned pos = atomicAdd(&g_count[row], 1u);
    if (pos < DEG_CAP)
        reinterpret_cast<unsigned short*>(g_list4)[row * DEG_CAP + pos] =
            (unsigned short)tgt;
}

// ---------------------------------------------------------------------------
// Warp-distributed presence bitmap over the 4096 possible targets:
// lane (v>>7) owns value v, in word (v>>5)&3, bit v&31.
// ---------------------------------------------------------------------------
__device__ __forceinline__ unsigned test_present(
    unsigned e, unsigned p0, unsigned p1, unsigned p2, unsigned p3) {
    unsigned w = (e >> 5) & 3u;
    unsigned pw = (w == 0u) ? p0 : (w == 1u) ? p1 : (w == 2u) ? p2 : p3;
    unsigned bit = (pw >> (e & 31u)) & 1u;
    return __shfl_sync(0xffffffffu, bit, e >> 7);   // owner lane's answer
}

__device__ __forceinline__ void set_present(
    unsigned e, bool cond, unsigned lane,
    unsigned& p0, unsigned& p1, unsigned& p2, unsigned& p3) {
    if (cond && lane == (e >> 7)) {
        unsigned b = 1u << (e & 31u);
        unsigned w = (e >> 5) & 3u;
        if      (w == 0u) p0 |= b;
        else if (w == 1u) p1 |= b;
        else if (w == 2u) p2 |= b;
        else              p3 |= b;
    }
}

// ---------------------------------------------------------------------------
// Kernel 2: one warp per (b,i) row, lane == t.
//   acc[t] = yb[b,i,t] (identity) + sum over DISTINCT listed targets j of
//            yb[b,j,t]   (exact jnp .at[].set(1.0) semantics via the warp
//            bitmap: first occurrence wins, later copies suppressed)
//   reg   += relu(yb[b,i,t+1] - acc[t]), t in [0,31)
// EARLY EXIT: y >= 0 so acc is monotone; once every lane has acc >= ynext the
// remaining relu terms are exactly 0 (processed set is a subset of the
// distinct set, so this holds regardless of append order).
// ---------------------------------------------------------------------------
__global__ void nil_agg_kernel(const float* __restrict__ y,
                               float* __restrict__ out) {
    const unsigned FULL = 0xffffffffu;
    unsigned gwarp = (blockIdx.x * blockDim.x + threadIdx.x) >> 5;  // row id
    unsigned lane  = threadIdx.x & 31;

    unsigned b = gwarp >> 12;        // / M
    unsigned i = gwarp & (M - 1);

    const ushort4* lst4 = g_list4 + (size_t)gwarp * (DEG_CAP / 4);
    const float* yb = y + (size_t)b * (M * T);

    // ---- front-issue all independent loads ----
    int deg = (int)g_count[gwarp];           // warp-uniform 4B load
    ushort4 q0 = lst4[0];                    // warp-uniform 8B load
    float self = yb[(size_t)i * T + lane];   // coalesced 128B load

    if (lane == 0) g_count[gwarp] = 0u;      // self-clean for next replay
    if (deg > DEG_CAP) deg = DEG_CAP;

    float acc = self;                        // identity term
    float ynext = __shfl_down_sync(FULL, self, 1);
    bool tvalid = (lane < 31);

    unsigned p0 = 0u, p1 = 0u, p2 = 0u, p3 = 0u;   // presence bitmap

    // ---- quad 0: unconditional gathers, intra-quad dedup only ----
    {
        unsigned e0 = q0.x, e1 = q0.y, e2 = q0.z, e3 = q0.w;
        float v0 = yb[(size_t)e0 * T + lane];
        float v1 = yb[(size_t)e1 * T + lane];
        float v2 = yb[(size_t)e2 * T + lane];
        float v3 = yb[(size_t)e3 * T + lane];
        bool u1 = (e1 != e0);
        bool u2 = (e2 != e0) & (e2 != e1);
        bool u3 = (e3 != e0) & (e3 != e1) & (e3 != e2);
        if (deg > 0)       acc += v0;
        if (deg > 1 && u1) acc += v1;
        if (deg > 2 && u2) acc += v2;
        if (deg > 3 && u3) acc += v3;
        set_present(e0, deg > 0, lane, p0, p1, p2, p3);
        set_present(e1, deg > 1, lane, p0, p1, p2, p3);
        set_present(e2, deg > 2, lane, p0, p1, p2, p3);
        set_present(e3, deg > 3, lane, p0, p1, p2, p3);
    }

    // ---- remaining quads with monotone early exit + bitmap dedup ----
    unsigned pend = __ballot_sync(FULL, tvalid && acc < ynext);
    for (int k = 4; k < deg && pend; k += 4) {
        ushort4 q = lst4[k >> 2];
        unsigned e0 = q.x, e1 = q.y, e2 = q.z, e3 = q.w;
        float v0 = yb[(size_t)e0 * T + lane];
        float v1 = yb[(size_t)e1 * T + lane];
        float v2 = yb[(size_t)e2 * T + lane];
        float v3 = yb[(size_t)e3 * T + lane];
        // prior-quad duplicate tests (4 independent shfls)
        unsigned d0 = test_present(e0, p0, p1, p2, p3);
        unsigned d1 = test_present(e1, p0, p1, p2, p3);
        unsigned d2 = test_present(e2, p0, p1, p2, p3);
        unsigned d3 = test_present(e3, p0, p1, p2, p3);
        // intra-quad uniqueness
        bool u1 = (e1 != e0);
        bool u2 = (e2 != e0) & (e2 != e1);
        bool u3 = (e3 != e0) & (e3 != e1) & (e3 != e2);
        if (!d0)                            acc += v0;  // k < deg by loop
        if (k + 1 < deg && !d1 && u1)       acc += v1;
        if (k + 2 < deg && !d2 && u2)       acc += v2;
        if (k + 3 < deg && !d3 && u3)       acc += v3;
        set_present(e0, true,        lane, p0, p1, p2, p3);
        set_present(e1, k + 1 < deg, lane, p0, p1, p2, p3);
        set_present(e2, k + 2 < deg, lane, p0, p1, p2, p3);
        set_present(e3, k + 3 < deg, lane, p0, p1, p2, p3);
        pend = __ballot_sync(FULL, tvalid && acc < ynext);
    }

    // ---- reduce only if some lane can contribute (pend warp-uniform) ----
    float wsum = 0.0f;
    if (pend) {
        float r = tvalid ? fmaxf(ynext - acc, 0.0f) : 0.0f;
        #pragma unroll
        for (int o = 16; o > 0; o >>= 1)
            r += __shfl_down_sync(FULL, r, o);
        wsum = r;
    }

    // block reduce (8 warps/block) -> at most one atomic per block
    __shared__ float sred[8];
    unsigned wib = threadIdx.x >> 5;
    if (lane == 0) sred[wib] = wsum;
    __syncthreads();
    if (threadIdx.x < 8) {
        float v = sred[threadIdx.x];
        #pragma unroll
        for (int o = 4; o > 0; o >>= 1)
            v += __shfl_down_sync(0x000000ffu, v, o);
        if (threadIdx.x == 0 && v != 0.0f) atomicAdd(out, v);
    }
}

// ---------------------------------------------------------------------------
// kernel_launch: build -> aggregate. Plain launches, no allocs/syncs.
// ---------------------------------------------------------------------------
extern "C" void kernel_launch(void* const* d_in, const int* in_sizes, int n_in,
                              void* d_out, int out_size) {
    (void)in_sizes; (void)n_in; (void)out_size;
    const float* y   = (const float*)d_in[0];
    const int*   coo = (const int*)d_in[1];
    float*       out = (float*)d_out;

    nil_build_kernel<<<(BS * E) / 256, 256>>>(coo, out);
    nil_agg_kernel<<<NROWS / 8, 256>>>(y, out);
}

// round 9
// speedup vs baseline: 2.4337x; 1.1792x over previous
#include <cuda_runtime.h>
#include <cstdint>

// Problem constants (fixed by setup_inputs)
#define BS 8
#define M  4096
#define T  32
#define E  65536
#define NROWS (BS * M)          // 32768
#define DEG_CAP 64              // Poisson(16) row degree; P(>64) ~ 1e-20

// Scratch. Device globals start zeroed at module load; agg resets counts after
// consuming them, so every replay starts clean. Stale list tails are never
// read (bounded by deg) and are always < M.
__device__ unsigned g_count[NROWS];                 // per-row edge counts
__device__ ushort4  g_list4[NROWS * (DEG_CAP / 4)]; // packed u16 target lists

// ---------------------------------------------------------------------------
// Kernel 1: append every edge (dups included -> dedup lazily in agg). ONE
// atomic per edge — build is atomic-throughput bound, minimal form.
// A_coo is int32, layout (bs, 2, E) row-major.
// ---------------------------------------------------------------------------
__global__ void nil_build_kernel(const int* __restrict__ coo,
                                 float* __restrict__ out) {
    unsigned tid = blockIdx.x * blockDim.x + threadIdx.x;  // < BS*E
    if (tid == 0) *out = 0.0f;
    unsigned b = tid >> 16;        // / E
    unsigned e = tid & (E - 1);
    int s = coo[(size_t)b * 2 * E + e];
    int t = coo[(size_t)b * 2 * E + E + e];
    unsigned src = (unsigned)s & (M - 1);   // % M (power of two)
    unsigned tgt = (unsigned)t & (M - 1);
    unsigned row = b * M + src;

    unsigned pos = atomicAdd(&g_count[row], 1u);
    if (pos < DEG_CAP)
        reinterpret_cast<unsigned short*>(g_list4)[row * DEG_CAP + pos] =
            (unsigned short)tgt;
}

// ---------------------------------------------------------------------------
// Kernel 2: one warp per (b,i) row, lane == t.
//   acc[t] = yb[b,i,t] (identity) + sum over DISTINCT listed targets j of
//            yb[b,j,t]  (first occurrence wins == jnp .at[].set(1.0))
//   reg   += relu(yb[b,i,t+1] - acc[t]), t in [0,31)
//
// Common path (~95% of warps): quad 0 only, intra-quad dedup = 3 compares.
// Rare path (warp-uniform): one __match_any_sync pass builds a 64-bit keep
// mask; later quads predicate adds on warp-uniform keep bits.
// EARLY EXIT is exact: y >= 0 -> acc monotone; once acc >= ynext on all lanes
// every remaining relu term is 0 (processed set is a subset of distinct set).
// ---------------------------------------------------------------------------
__global__ void nil_agg_kernel(const float* __restrict__ y,
                               float* __restrict__ out) {
    const unsigned FULL = 0xffffffffu;
    unsigned gwarp = (blockIdx.x * blockDim.x + threadIdx.x) >> 5;  // row id
    unsigned lane  = threadIdx.x & 31;

    unsigned b = gwarp >> 12;        // / M
    unsigned i = gwarp & (M - 1);

    const ushort4* lst4 = g_list4 + (size_t)gwarp * (DEG_CAP / 4);
    const unsigned short* lst =
        reinterpret_cast<const unsigned short*>(g_list4) + (size_t)gwarp * DEG_CAP;
    const float* yb = y + (size_t)b * (M * T);

    // ---- front-issue all independent loads ----
    int deg = (int)g_count[gwarp];           // warp-uniform 4B load
    ushort4 q0 = lst4[0];                    // warp-uniform 8B load
    float self = yb[(size_t)i * T + lane];   // coalesced 128B load

    if (lane == 0) g_count[gwarp] = 0u;      // self-clean for next replay
    if (deg > DEG_CAP) deg = DEG_CAP;

    float acc = self;                        // identity term
    float ynext = __shfl_down_sync(FULL, self, 1);
    bool tvalid = (lane < 31);

    // ---- quad 0: gathers + intra-quad dedup (no earlier entries exist) ----
    {
        unsigned e0 = q0.x, e1 = q0.y, e2 = q0.z, e3 = q0.w;
        float v0 = yb[(size_t)e0 * T + lane];
        float v1 = yb[(size_t)e1 * T + lane];
        float v2 = yb[(size_t)e2 * T + lane];
        float v3 = yb[(size_t)e3 * T + lane];
        bool u1 = (e1 != e0);
        bool u2 = (e2 != e0) & (e2 != e1);
        bool u3 = (e3 != e0) & (e3 != e1) & (e3 != e2);
        if (deg > 0)       acc += v0;
        if (deg > 1 && u1) acc += v1;
        if (deg > 2 && u2) acc += v2;
        if (deg > 3 && u3) acc += v3;
    }

    unsigned pend = __ballot_sync(FULL, tvalid && acc < ynext);
    float wsum = 0.0f;

    if (pend && deg > 4) {                   // warp-uniform rare path (~5%)
        // ---- build 64-bit first-occurrence keep mask, once ----
        // Lane l owns entries l and l+32. Sentinels unique per lane, disjoint
        // from real values (<4096) and from each other.
        unsigned e_lo = (lane < (unsigned)deg) ? (unsigned)lst[lane]
                                               : (0x10000u | lane);
        unsigned m_lo = __match_any_sync(FULL, e_lo);
        bool k_lo = (lane < (unsigned)deg) &&
                    ((m_lo & ((1u << lane) - 1u)) == 0u);
        unsigned long long keep =
            (unsigned long long)__ballot_sync(FULL, k_lo);

        if (deg > 32) {                      // warp-uniform, P ~ 1e-4
            unsigned e_hi = (lane + 32 < (unsigned)deg)
                                ? (unsigned)lst[lane + 32] : (0x20000u | lane);
            unsigned m_hi = __match_any_sync(FULL, e_hi);
            bool k_hi = (lane + 32 < (unsigned)deg) &&
                        ((m_hi & ((1u << lane) - 1u)) == 0u);
            bool dup = false;                // cross-half duplicate test
            #pragma unroll
            for (int l = 0; l < 32; ++l) {
                unsigned v = __shfl_sync(FULL, e_lo, l);
                dup = dup || (v == e_hi);
            }
            k_hi = k_hi && !dup;
            keep |= ((unsigned long long)__ballot_sync(FULL, k_hi)) << 32;
        }

        // ---- remaining quads, keep-bit predicated, early exit between ----
        for (int k = 4; k < deg && pend; k += 4) {
            ushort4 q = lst4[k >> 2];
            float v0 = yb[(size_t)q.x * T + lane];
            float v1 = yb[(size_t)q.y * T + lane];
            float v2 = yb[(size_t)q.z * T + lane];
            float v3 = yb[(size_t)q.w * T + lane];
            unsigned kb = (unsigned)(keep >> k) & 0xFu;  // warp-uniform
            if (kb & 1u) acc += v0;
            if (kb & 2u) acc += v1;
            if (kb & 4u) acc += v2;
            if (kb & 8u) acc += v3;
            pend = __ballot_sync(FULL, tvalid && acc < ynext);
        }
    }

    // ---- reduce only if some lane can still contribute ----
    if (pend) {
        float r = tvalid ? fmaxf(ynext - acc, 0.0f) : 0.0f;
        #pragma unroll
        for (int o = 16; o > 0; o >>= 1)
            r += __shfl_down_sync(FULL, r, o);
        wsum = r;
    }

    // block reduce (8 warps/block) -> at most one atomic per block
    __shared__ float sred[8];
    unsigned wib = threadIdx.x >> 5;
    if (lane == 0) sred[wib] = wsum;
    __syncthreads();
    if (threadIdx.x < 8) {
        float v = sred[threadIdx.x];
        #pragma unroll
        for (int o = 4; o > 0; o >>= 1)
            v += __shfl_down_sync(0x000000ffu, v, o);
        if (threadIdx.x == 0 && v != 0.0f) atomicAdd(out, v);
    }
}

// ---------------------------------------------------------------------------
// kernel_launch: build -> aggregate. Plain launches, no allocs/syncs.
// ---------------------------------------------------------------------------
extern "C" void kernel_launch(void* const* d_in, const int* in_sizes, int n_in,
                              void* d_out, int out_size) {
    (void)in_sizes; (void)n_in; (void)out_size;
    const float* y   = (const float*)d_in[0];
    const int*   coo = (const int*)d_in[1];
    float*       out = (float*)d_out;

    nil_build_kernel<<<(BS * E) / 256, 256>>>(coo, out);
    nil_agg_kernel<<<NROWS / 8, 256>>>(y, out);
}

// round 10
// speedup vs baseline: 2.4411x; 1.0030x over previous
#include <cuda_runtime.h>
#include <cstdint>

// Problem constants (fixed by setup_inputs)
#define BS 8
#define M  4096
#define T  32
#define E  65536
#define NROWS (BS * M)          // 32768
#define DEG_CAP 64              // Poisson(16) row degree; P(>64) ~ 1e-20

// Scratch. Device globals start zeroed at module load; agg resets counts after
// consuming them, so every replay starts clean. Stale list tails are never
// read (bounded by deg) and are always < M.
__device__ unsigned g_count[NROWS];                 // per-row edge counts
__device__ ushort4  g_list4[NROWS * (DEG_CAP / 4)]; // packed u16 target lists

// ---------------------------------------------------------------------------
// Kernel 1: append every edge (dups included -> dedup lazily in agg). ONE
// atomic per edge — build is atomic-throughput bound, minimal form.
// A_coo is int32, layout (bs, 2, E) row-major.
// ---------------------------------------------------------------------------
__global__ void nil_build_kernel(const int* __restrict__ coo,
                                 float* __restrict__ out) {
    unsigned tid = blockIdx.x * blockDim.x + threadIdx.x;  // < BS*E
    if (tid == 0) *out = 0.0f;
    unsigned b = tid >> 16;        // / E
    unsigned e = tid & (E - 1);
    int s = coo[(size_t)b * 2 * E + e];
    int t = coo[(size_t)b * 2 * E + E + e];
    unsigned src = (unsigned)s & (M - 1);   // % M (power of two)
    unsigned tgt = (unsigned)t & (M - 1);
    unsigned row = b * M + src;

    unsigned pos = atomicAdd(&g_count[row], 1u);
    if (pos < DEG_CAP)
        reinterpret_cast<unsigned short*>(g_list4)[row * DEG_CAP + pos] =
            (unsigned short)tgt;
}

__device__ __forceinline__ void add4(float4& a, const float4& v) {
    a.x += v.x; a.y += v.y; a.z += v.z; a.w += v.w;
}

// ---------------------------------------------------------------------------
// Kernel 2: one warp per FOUR consecutive rows. Lane l = (group g=l/8 -> row
// 4w+g, chunk c=l%8 -> t in [4c, 4c+3]) holding acc as float4.
//   acc[t] = yb[b,i,t] (identity) + sum over DISTINCT listed targets j of
//            yb[b,j,t]  (first occurrence wins == jnp .at[].set(1.0))
//   reg   += relu(yb[b,i,t+1] - acc[t]), t in [0,31)
// Fast path: quad 0 only (intra-quad dedup = 3 compares); rows whose lanes
// all satisfy acc >= ynext contribute EXACTLY 0 (y >= 0 -> acc monotone) and
// are done. Live rows (~4%) take a warp-converged slow path: transpose acc to
// lane=t layout, build a 64-bit first-occurrence keep mask via match_any,
// finish the list with keep-predicated gathers + early exit, reduce relu.
// ---------------------------------------------------------------------------
__global__ void nil_agg_kernel(const float* __restrict__ y,
                               float* __restrict__ out) {
    const unsigned FULL = 0xffffffffu;
    unsigned warp = (blockIdx.x * blockDim.x + threadIdx.x) >> 5; // 0..8191
    unsigned lane = threadIdx.x & 31;
    unsigned g = lane >> 3, c = lane & 7;

    unsigned row0 = warp << 2;        // 4 consecutive rows, same batch (M%4==0)
    unsigned row  = row0 + g;
    unsigned b    = row0 >> 12;       // / M
    const float*  yb  = y + (size_t)b * (M * T);
    const float4* yb4 = reinterpret_cast<const float4*>(yb);

    // ---- front-issue independent loads ----
    int deg = (int)g_count[row];                       // group-uniform 4B
    ushort4 q0 = g_list4[(size_t)row * (DEG_CAP / 4)]; // group-uniform 8B
    float4 self4 = yb4[(size_t)(row & (M - 1)) * (T / 4) + c]; // 512B coalesced

    if (lane < 4) g_count[row0 + lane] = 0u;  // self-clean (coalesced 16B)
    if (deg > DEG_CAP) deg = DEG_CAP;

    float4 acc = self4;                       // identity term
    // ynext for t=4c..4c+3: (self.y, self.z, self.w, next-lane self.x).
    // c==7's 4th component (t=31) is invalid and masked below, so the
    // cross-group garbage from shfl_down is never used.
    float n3 = __shfl_down_sync(FULL, self4.x, 1);

    // ---- quad 0: 4 gathers (one LDG.128 per lane, 4 rows per warp instr) ----
    {
        unsigned e0 = q0.x, e1 = q0.y, e2 = q0.z, e3 = q0.w;
        float4 v0 = yb4[e0 * (T / 4) + c];
        float4 v1 = yb4[e1 * (T / 4) + c];
        float4 v2 = yb4[e2 * (T / 4) + c];
        float4 v3 = yb4[e3 * (T / 4) + c];
        bool u1 = (e1 != e0);
        bool u2 = (e2 != e0) & (e2 != e1);
        bool u3 = (e3 != e0) & (e3 != e1) & (e3 != e2);
        if (deg > 0)       add4(acc, v0);
        if (deg > 1 && u1) add4(acc, v1);
        if (deg > 2 && u2) add4(acc, v2);
        if (deg > 3 && u3) add4(acc, v3);
    }

    // ---- liveness: any t in this lane with acc[t] < ynext[t]? ----
    bool live = (acc.x < self4.y) | (acc.y < self4.z) | (acc.z < self4.w) |
                ((c < 7) & (acc.w < n3));
    unsigned pend = __ballot_sync(FULL, live);

    float wsum = 0.0f;                        // meaningful on lane 0 only
    if (pend) {
        // ---- warp-converged slow path, one live row at a time ----
        #pragma unroll
        for (int gg = 0; gg < 4; ++gg) {
            if (!((pend >> (8 * gg)) & 0xFFu)) continue;
            unsigned r_row = row0 + gg;
            int dg = __shfl_sync(FULL, deg, gg * 8);

            // transpose this row's acc into lane=t layout
            unsigned srcl = gg * 8 + (lane >> 2);
            float a0 = __shfl_sync(FULL, acc.x, srcl);
            float a1 = __shfl_sync(FULL, acc.y, srcl);
            float a2 = __shfl_sync(FULL, acc.z, srcl);
            float a3 = __shfl_sync(FULL, acc.w, srcl);
            unsigned sel = lane & 3;
            float accT = (sel == 0) ? a0 : (sel == 1) ? a1
                       : (sel == 2) ? a2 : a3;

            float selfT = yb[(size_t)(r_row & (M - 1)) * T + lane];
            float ynT = __shfl_down_sync(FULL, selfT, 1);
            bool tv = (lane < 31);

            const unsigned short* lst =
                reinterpret_cast<const unsigned short*>(g_list4) +
                (size_t)r_row * DEG_CAP;
            const ushort4* l4 = g_list4 + (size_t)r_row * (DEG_CAP / 4);

            // 64-bit first-occurrence keep mask (bits 0..3 == intra-quad
            // dedup already applied in quad 0 -> consistent continuation)
            unsigned e_lo = (lane < (unsigned)dg) ? (unsigned)lst[lane]
                                                  : (0x10000u | lane);
            unsigned m_lo = __match_any_sync(FULL, e_lo);
            bool k_lo = (lane < (unsigned)dg) &&
                        ((m_lo & ((1u << lane) - 1u)) == 0u);
            unsigned long long keep =
                (unsigned long long)__ballot_sync(FULL, k_lo);
            if (dg > 32) {                    // warp-uniform, P ~ 1e-4
                unsigned e_hi = (lane + 32 < (unsigned)dg)
                                    ? (unsigned)lst[lane + 32]
                                    : (0x20000u | lane);
                unsigned m_hi = __match_any_sync(FULL, e_hi);
                bool k_hi = (lane + 32 < (unsigned)dg) &&
                            ((m_hi & ((1u << lane) - 1u)) == 0u);
                bool dup = false;
                #pragma unroll
                for (int l = 0; l < 32; ++l) {
                    unsigned v = __shfl_sync(FULL, e_lo, l);
                    dup = dup || (v == e_hi);
                }
                k_hi = k_hi && !dup;
                keep |= ((unsigned long long)__ballot_sync(FULL, k_hi)) << 32;
            }

            unsigned pnd = __ballot_sync(FULL, tv && accT < ynT);
            for (int k = 4; k < dg && pnd; k += 4) {
                ushort4 q = l4[k >> 2];
                float w0 = yb[(size_t)q.x * T + lane];
                float w1 = yb[(size_t)q.y * T + lane];
                float w2 = yb[(size_t)q.z * T + lane];
                float w3 = yb[(size_t)q.w * T + lane];
                unsigned kb = (unsigned)(keep >> k) & 0xFu;  // warp-uniform
                if (kb & 1u) accT += w0;
                if (kb & 2u) accT += w1;
                if (kb & 4u) accT += w2;
                if (kb & 8u) accT += w3;
                pnd = __ballot_sync(FULL, tv && accT < ynT);
            }
            if (pnd) {
                float rr = tv ? fmaxf(ynT - accT, 0.0f) : 0.0f;
                #pragma unroll
                for (int o = 16; o > 0; o >>= 1)
                    rr += __shfl_down_sync(FULL, rr, o);
                wsum += rr;                   // total lands on lane 0
            }
        }
    }

    // block reduce (8 warps/block) -> at most one atomic per block
    __shared__ float sred[8];
    unsigned wib = threadIdx.x >> 5;
    if (lane == 0) sred[wib] = wsum;
    __syncthreads();
    if (threadIdx.x < 8) {
        float v = sred[threadIdx.x];
        #pragma unroll
        for (int o = 4; o > 0; o >>= 1)
            v += __shfl_down_sync(0x000000ffu, v, o);
        if (threadIdx.x == 0 && v != 0.0f) atomicAdd(out, v);
    }
}

// ---------------------------------------------------------------------------
// kernel_launch: build -> aggregate. Plain launches, no allocs/syncs.
// ---------------------------------------------------------------------------
extern "C" void kernel_launch(void* const* d_in, const int* in_sizes, int n_in,
                              void* d_out, int out_size) {
    (void)in_sizes; (void)n_in; (void)out_size;
    const float* y   = (const float*)d_in[0];
    const int*   coo = (const int*)d_in[1];
    float*       out = (float*)d_out;

    nil_build_kernel<<<(BS * E) / 256, 256>>>(coo, out);
    // 32768 rows / 4 rows per warp / 8 warps per block = 1024 blocks
    nil_agg_kernel<<<NROWS / 32, 256>>>(y, out);
}